// round 5
// baseline (speedup 1.0000x reference)
#include <cuda_runtime.h>
#include <cuda_bf16.h>
#include <math.h>
#include <stdint.h>

#define E_EDGES 400000
#define NGROUPS 25000

// ===========================================================================
// PTX helpers (sm_80-class only: cp.async, ldmatrix, mma.sync — NO tcgen05,
// which is rejected by this toolchain's .target sm_103)
// ===========================================================================
__device__ __forceinline__ uint32_t smem_u32(const void* p) {
    uint32_t a;
    asm("{ .reg .u64 t; cvta.to.shared.u64 t, %1; cvt.u32.u64 %0, t; }"
        : "=r"(a) : "l"(p));
    return a;
}

#define CP_ASYNC16(sm, gm) \
    asm volatile("cp.async.cg.shared.global [%0], [%1], 16;" \
        :: "r"(sm), "l"(gm) : "memory")
#define CP_COMMIT() asm volatile("cp.async.commit_group;" ::: "memory")
#define CP_WAIT(n)  asm volatile("cp.async.wait_group %0;" :: "n"(n) : "memory")

__device__ __forceinline__ void ldsm_x4(uint32_t (&d)[4], uint32_t addr) {
    asm volatile("ldmatrix.sync.aligned.m8n8.x4.shared.b16 {%0,%1,%2,%3}, [%4];"
        : "=r"(d[0]), "=r"(d[1]), "=r"(d[2]), "=r"(d[3]) : "r"(addr));
}
__device__ __forceinline__ void ldsm_x2(uint32_t (&d)[2], uint32_t addr) {
    asm volatile("ldmatrix.sync.aligned.m8n8.x2.shared.b16 {%0,%1}, [%2];"
        : "=r"(d[0]), "=r"(d[1]) : "r"(addr));
}

#define MMA16816(d, a, b) \
    asm volatile("mma.sync.aligned.m16n8k16.row.col.f32.bf16.bf16.f32 " \
        "{%0,%1,%2,%3}, {%4,%5,%6,%7}, {%8,%9}, {%0,%1,%2,%3};" \
        : "+f"((d)[0]), "+f"((d)[1]), "+f"((d)[2]), "+f"((d)[3]) \
        : "r"((a)[0]), "r"((a)[1]), "r"((a)[2]), "r"((a)[3]), \
          "r"((b)[0]), "r"((b)[1]))

__device__ __forceinline__ uint32_t sw128(uint32_t off) {
    return off ^ ((off >> 3) & 0x70);
}

// ===========================================================================
// Scratch globals (no cudaMalloc allowed)
// ===========================================================================
__device__ __nv_bfloat16 g_hiA[(size_t)E_EDGES * 256];
__device__ __nv_bfloat16 g_loA[(size_t)E_EDGES * 256];
__device__ __nv_bfloat16 g_hiB[(size_t)E_EDGES * 256];
__device__ __nv_bfloat16 g_loB[(size_t)E_EDGES * 256];
__device__ float g_q  [(size_t)E_EDGES * 32];
__device__ float g_xnk[(size_t)E_EDGES * 96];

__device__ float g_W2q [256 * 32];   // W2 @ Wqk  (fp32, [k][n])
__device__ float g_Wcat[256 * 96];   // [W2 | W2@Wk] (fp32, [k][n])
// Transposed + split weights, [n][k] layout (K contiguous)
__device__ __nv_bfloat16 g_W0t_hi[256 * 256], g_W0t_lo[256 * 256];
__device__ __nv_bfloat16 g_W1t_hi[256 * 256], g_W1t_lo[256 * 256];
__device__ __nv_bfloat16 g_W2qt_hi[32 * 256], g_W2qt_lo[32 * 256];
__device__ __nv_bfloat16 g_Wct_hi[96 * 256],  g_Wct_lo[96 * 256];

__device__ __forceinline__ void split2(float v, __nv_bfloat16& h, __nv_bfloat16& l) {
    h = __float2bfloat16_rn(v);
    l = __float2bfloat16_rn(v - __bfloat162float(h));
}

// ===========================================================================
// prep1: fold head projections: g_W2q = W2@Wqk, g_Wcat = [W2 | W2@Wk]
// ===========================================================================
__global__ void prep_fold(const float* __restrict__ W2,
                          const float* __restrict__ Wqk,
                          const float* __restrict__ Wk) {
    __shared__ float sQ[64 * 32];
    __shared__ float sK[64 * 32];
    int tid = threadIdx.x;
    for (int i = tid; i < 64 * 32; i += 256) { sQ[i] = Wqk[i]; sK[i] = Wk[i]; }
    __syncthreads();
    int r = tid;
    float w2r[64];
#pragma unroll
    for (int j = 0; j < 64; ++j) w2r[j] = W2[r * 64 + j];
#pragma unroll 4
    for (int c = 0; c < 32; ++c) {
        float aq = 0.f, ak = 0.f;
#pragma unroll
        for (int j = 0; j < 64; ++j) {
            aq = fmaf(w2r[j], sQ[j * 32 + c], aq);
            ak = fmaf(w2r[j], sK[j * 32 + c], ak);
        }
        g_W2q[r * 32 + c]       = aq;
        g_Wcat[r * 96 + 64 + c] = ak;
    }
#pragma unroll
    for (int j = 0; j < 64; ++j) g_Wcat[r * 96 + j] = w2r[j];
}

// ===========================================================================
// prep2: transpose to [n][k] and split all GEMM weights to bf16 hi/lo
// ===========================================================================
__global__ void prep_transpose_split(const float* __restrict__ W0,
                                     const float* __restrict__ W1) {
    int t = blockIdx.x * 256 + threadIdx.x;
    int o = t >> 8, i = t & 255;
    __nv_bfloat16 h, l;
    split2(W0[i * 256 + o], h, l);  g_W0t_hi[t] = h;  g_W0t_lo[t] = l;
    split2(W1[i * 256 + o], h, l);  g_W1t_hi[t] = h;  g_W1t_lo[t] = l;
    if (o < 32) { split2(g_W2q[i * 32 + o], h, l);  g_W2qt_hi[t] = h; g_W2qt_lo[t] = l; }
    if (o < 96) { split2(g_Wcat[i * 96 + o], h, l); g_Wct_hi[t] = h;  g_Wct_lo[t] = l; }
}

// ===========================================================================
// convert fp32 activations -> bf16 hi/lo (one float4 per thread)
// ===========================================================================
__global__ void convert_split(const float* __restrict__ X,
                              __nv_bfloat16* __restrict__ hi,
                              __nv_bfloat16* __restrict__ lo) {
    size_t i = (size_t)blockIdx.x * blockDim.x + threadIdx.x;
    float4 v = ((const float4*)X)[i];
    float f[4] = {v.x, v.y, v.z, v.w};
    uint32_t hw[2], lw[2];
#pragma unroll
    for (int j = 0; j < 2; ++j) {
        __nv_bfloat16 h0, l0, h1, l1;
        split2(f[2 * j], h0, l0);
        split2(f[2 * j + 1], h1, l1);
        hw[j] = (uint32_t)__bfloat16_as_ushort(h0) | ((uint32_t)__bfloat16_as_ushort(h1) << 16);
        lw[j] = (uint32_t)__bfloat16_as_ushort(l0) | ((uint32_t)__bfloat16_as_ushort(l1) << 16);
    }
    ((uint2*)hi)[i] = make_uint2(hw[0], hw[1]);
    ((uint2*)lo)[i] = make_uint2(lw[0], lw[1]);
}

// ===========================================================================
// HMMA GEMM: C[M, N_TOT] = op( A[M,256] @ Bt[N_TOT,256]^T ), bf16x3 scheme:
//   C = Ah*Bh + Al*Bh + Ah*Bl   (3 passes over K=256 -> K_eff=768)
// BM=128, BN per template, BK=64, 256 threads = 8 warps laid out 4(M) x 2(N).
// Warp tile = 32 x (BN/2) via m16n8k16. Double-buffered cp.async.
// SPLIT_RELU: relu + re-split hi/lo bf16 (width 256). Else fp32 store (W_OUT).
// ===========================================================================
template <int BN, int W_OUT, bool SPLIT_RELU>
__global__ void __launch_bounds__(256)
hmma_gemm(const __nv_bfloat16* __restrict__ Ah, const __nv_bfloat16* __restrict__ Al,
          const __nv_bfloat16* __restrict__ Bh, const __nv_bfloat16* __restrict__ Bl,
          void* __restrict__ outHi, __nv_bfloat16* __restrict__ outLo) {
    constexpr int NB      = BN / 16;          // mma n-tiles per warp (warp covers BN/2 cols)
    constexpr int A_BYTES = 128 * 128;        // 128 rows x 64 bf16 (128B)
    constexpr int B_BYTES = BN * 128;

    extern __shared__ char smem[];
    const uint32_t sA0 = smem_u32(smem);
    const uint32_t sB0 = sA0 + 2 * A_BYTES;

    const int tid  = threadIdx.x;
    const int lane = tid & 31;
    const int wid  = tid >> 5;
    const int m0w  = (wid & 3) * 32;
    const int n0w  = (wid >> 2) * (BN / 2);
    const int row0 = blockIdx.x * 128;
    const int col0 = blockIdx.y * BN;

    float acc[2][NB][4];
#pragma unroll
    for (int mi = 0; mi < 2; ++mi)
#pragma unroll
        for (int ni = 0; ni < NB; ++ni)
#pragma unroll
            for (int v = 0; v < 4; ++v) acc[mi][ni][v] = 0.f;

    auto loadTile = [&](int it, int buf) {
        const int pass = it >> 2;
        const int kk   = (it & 3) << 6;
        const __nv_bfloat16* ga = (pass == 1 ? Al : Ah) + (size_t)row0 * 256 + kk;
        const __nv_bfloat16* gb = (pass == 2 ? Bl : Bh) + (size_t)col0 * 256 + kk;
        const uint32_t da = sA0 + buf * A_BYTES;
#pragma unroll
        for (int i = tid; i < 1024; i += 256) {
            int r = i >> 3, c = i & 7;
            CP_ASYNC16(da + sw128(r * 128 + c * 16), ga + (size_t)r * 256 + c * 8);
        }
        const uint32_t db = sB0 + buf * B_BYTES;
#pragma unroll
        for (int i = tid; i < BN * 8; i += 256) {
            int r = i >> 3, c = i & 7;
            CP_ASYNC16(db + sw128(r * 128 + c * 16), gb + (size_t)r * 256 + c * 8);
        }
    };

    loadTile(0, 0);
    CP_COMMIT();

#pragma unroll 1
    for (int it = 0; it < 12; ++it) {
        if (it < 11) {
            loadTile(it + 1, (it + 1) & 1);
            CP_COMMIT();
            CP_WAIT(1);
        } else {
            CP_WAIT(0);
        }
        __syncthreads();

        const uint32_t da = sA0 + (it & 1) * A_BYTES;
        const uint32_t db = sB0 + (it & 1) * B_BYTES;
#pragma unroll
        for (int ks = 0; ks < 4; ++ks) {
            uint32_t a[2][4];
#pragma unroll
            for (int mi = 0; mi < 2; ++mi)
                ldsm_x4(a[mi], da + sw128((m0w + mi * 16 + (lane & 15)) * 128 +
                                          ks * 32 + (lane >> 4) * 16));
            uint32_t b[NB][2];
#pragma unroll
            for (int ni = 0; ni < NB; ++ni)
                ldsm_x2(b[ni], db + sw128((n0w + ni * 8 + (lane & 7)) * 128 +
                                          ks * 32 + ((lane >> 3) & 1) * 16));
#pragma unroll
            for (int mi = 0; mi < 2; ++mi)
#pragma unroll
                for (int ni = 0; ni < NB; ++ni)
                    MMA16816(acc[mi][ni], a[mi], b[ni]);
        }
        __syncthreads();
    }

    // ---- epilogue ----
    const int rbase = row0 + m0w + (lane >> 2);
#pragma unroll
    for (int mi = 0; mi < 2; ++mi) {
        const int r0 = rbase + mi * 16;
#pragma unroll
        for (int ni = 0; ni < NB; ++ni) {
            const int c = col0 + n0w + ni * 8 + (lane & 3) * 2;
            if (SPLIT_RELU) {
                __nv_bfloat16* hi = (__nv_bfloat16*)outHi;
#pragma unroll
                for (int h = 0; h < 2; ++h) {
                    float v0 = fmaxf(acc[mi][ni][2 * h],     0.f);
                    float v1 = fmaxf(acc[mi][ni][2 * h + 1], 0.f);
                    __nv_bfloat16 h0, l0, h1, l1;
                    split2(v0, h0, l0);
                    split2(v1, h1, l1);
                    size_t off = (size_t)(r0 + h * 8) * 256 + c;
                    *(uint32_t*)(hi + off)    = (uint32_t)__bfloat16_as_ushort(h0) |
                                                ((uint32_t)__bfloat16_as_ushort(h1) << 16);
                    *(uint32_t*)(outLo + off) = (uint32_t)__bfloat16_as_ushort(l0) |
                                                ((uint32_t)__bfloat16_as_ushort(l1) << 16);
                }
            } else {
                float* of = (float*)outHi;
                *(float2*)(of + (size_t)r0 * W_OUT + c) =
                    make_float2(acc[mi][ni][0], acc[mi][ni][1]);
                *(float2*)(of + (size_t)(r0 + 8) * W_OUT + c) =
                    make_float2(acc[mi][ni][2], acc[mi][ni][3]);
            }
        }
    }
}

// ===========================================================================
// Edge finalize: one warp per edge.
//   s = sigmoid(dot(q,k)) * ppr;  atomicAdd(out[ppr_idx][:], xn[:] * s)
// g_xnk per edge: [0:64) x_neighbor, [64:96) k
// ===========================================================================
__global__ void edge_finalize(const float* __restrict__ ppr_scores,
                              const int* __restrict__ ppr_idx,
                              float* __restrict__ out) {
    int gtid = blockIdx.x * blockDim.x + threadIdx.x;
    int edge = gtid >> 5;
    int lane = gtid & 31;
    if (edge >= E_EDGES) return;

    const float* xnk = g_xnk + (size_t)edge * 96;
    float p = g_q[(size_t)edge * 32 + lane] * xnk[64 + lane];
#pragma unroll
    for (int off = 16; off > 0; off >>= 1)
        p += __shfl_xor_sync(0xffffffffu, p, off);

    float s = ppr_scores[edge] / (1.f + expf(-p));
    int g = ppr_idx[edge];
    atomicAdd(&out[(size_t)g * 64 + lane],      xnk[lane]      * s);
    atomicAdd(&out[(size_t)g * 64 + 32 + lane], xnk[32 + lane] * s);
}

// ===========================================================================
// Launch sequence (graph-capturable)
// ===========================================================================
extern "C" void kernel_launch(void* const* d_in, const int* in_sizes, int n_in,
                              void* d_out, int out_size) {
    const float* source_attr   = (const float*)d_in[0];
    const float* neighbor_attr = (const float*)d_in[1];
    const float* ppr_scores    = (const float*)d_in[2];
    const int*   ppr_idx       = (const int*)  d_in[3];
    const float* W0  = (const float*)d_in[5];
    const float* W1  = (const float*)d_in[6];
    const float* W2  = (const float*)d_in[7];
    const float* Wqk = (const float*)d_in[8];
    const float* Wk  = (const float*)d_in[9];
    float* out = (float*)d_out;

    __nv_bfloat16 *hiA, *loA, *hiB, *loB;
    __nv_bfloat16 *w0h, *w0l, *w1h, *w1l, *w2qh, *w2ql, *wch, *wcl;
    float *qbuf, *xnk;
    cudaGetSymbolAddress((void**)&hiA, g_hiA);
    cudaGetSymbolAddress((void**)&loA, g_loA);
    cudaGetSymbolAddress((void**)&hiB, g_hiB);
    cudaGetSymbolAddress((void**)&loB, g_loB);
    cudaGetSymbolAddress((void**)&qbuf, g_q);
    cudaGetSymbolAddress((void**)&xnk,  g_xnk);
    cudaGetSymbolAddress((void**)&w0h, g_W0t_hi);
    cudaGetSymbolAddress((void**)&w0l, g_W0t_lo);
    cudaGetSymbolAddress((void**)&w1h, g_W1t_hi);
    cudaGetSymbolAddress((void**)&w1l, g_W1t_lo);
    cudaGetSymbolAddress((void**)&w2qh, g_W2qt_hi);
    cudaGetSymbolAddress((void**)&w2ql, g_W2qt_lo);
    cudaGetSymbolAddress((void**)&wch, g_Wct_hi);
    cudaGetSymbolAddress((void**)&wcl, g_Wct_lo);

    // dynamic smem: 2*A(16KB) + 2*B
    constexpr int SM128 = 2 * 128 * 128 + 2 * 128 * 128;  // 65536
    constexpr int SM96  = 2 * 128 * 128 + 2 * 96 * 128;   // 57344
    constexpr int SM32  = 2 * 128 * 128 + 2 * 32 * 128;   // 40960
    cudaFuncSetAttribute(hmma_gemm<128, 256, true>,
                         cudaFuncAttributeMaxDynamicSharedMemorySize, SM128);
    cudaFuncSetAttribute(hmma_gemm<96, 96, false>,
                         cudaFuncAttributeMaxDynamicSharedMemorySize, SM96);
    cudaFuncSetAttribute(hmma_gemm<32, 32, false>,
                         cudaFuncAttributeMaxDynamicSharedMemorySize, SM32);

    const int MB = E_EDGES / 128;  // 3125 row tiles

    prep_fold<<<1, 256>>>(W2, Wqk, Wk);
    prep_transpose_split<<<256, 256>>>(W0, W1);
    cudaMemsetAsync(d_out, 0, (size_t)out_size * sizeof(float));

    // ---- source branch: only q survives ----
    convert_split<<<100000, 256>>>(source_attr, hiA, loA);
    hmma_gemm<128, 256, true ><<<dim3(MB, 2), 256, SM128>>>(hiA, loA, w0h, w0l, hiB, loB);
    hmma_gemm<128, 256, true ><<<dim3(MB, 2), 256, SM128>>>(hiB, loB, w1h, w1l, hiA, loA);
    hmma_gemm< 32,  32, false><<<dim3(MB, 1), 256, SM32 >>>(hiA, loA, w2qh, w2ql, qbuf, nullptr);

    // ---- neighbor branch: [x_neighbor(64) | k(32)] fused as N=96 ----
    convert_split<<<100000, 256>>>(neighbor_attr, hiA, loA);
    hmma_gemm<128, 256, true ><<<dim3(MB, 2), 256, SM128>>>(hiA, loA, w0h, w0l, hiB, loB);
    hmma_gemm<128, 256, true ><<<dim3(MB, 2), 256, SM128>>>(hiB, loB, w1h, w1l, hiA, loA);
    hmma_gemm< 96,  96, false><<<dim3(MB, 1), 256, SM96 >>>(hiA, loA, wch, wcl, xnk, nullptr);

    // ---- attention + segment scatter ----
    edge_finalize<<<(E_EDGES * 32 + 255) / 256, 256>>>(ppr_scores, ppr_idx, out);
}

// round 6
// speedup vs baseline: 1.1278x; 1.1278x over previous
#include <cuda_runtime.h>
#include <cuda_bf16.h>
#include <math.h>
#include <stdint.h>

#define E_EDGES 400000
#define NGROUPS 25000

// ===========================================================================
// PTX helpers (sm_80-class only: cp.async, ldmatrix, mma.sync — NO tcgen05,
// which is rejected by this toolchain's .target sm_103)
// ===========================================================================
__device__ __forceinline__ uint32_t smem_u32(const void* p) {
    uint32_t a;
    asm("{ .reg .u64 t; cvta.to.shared.u64 t, %1; cvt.u32.u64 %0, t; }"
        : "=r"(a) : "l"(p));
    return a;
}

#define CP_ASYNC16(sm, gm) \
    asm volatile("cp.async.cg.shared.global [%0], [%1], 16;" \
        :: "r"(sm), "l"(gm) : "memory")
#define CP_COMMIT() asm volatile("cp.async.commit_group;" ::: "memory")
#define CP_WAIT(n)  asm volatile("cp.async.wait_group %0;" :: "n"(n) : "memory")

__device__ __forceinline__ void ldsm_x4(uint32_t* d, uint32_t addr) {
    asm volatile("ldmatrix.sync.aligned.m8n8.x4.shared.b16 {%0,%1,%2,%3}, [%4];"
        : "=r"(d[0]), "=r"(d[1]), "=r"(d[2]), "=r"(d[3]) : "r"(addr));
}

#define MMA16816(d, a, b) \
    asm volatile("mma.sync.aligned.m16n8k16.row.col.f32.bf16.bf16.f32 " \
        "{%0,%1,%2,%3}, {%4,%5,%6,%7}, {%8,%9}, {%0,%1,%2,%3};" \
        : "+f"((d)[0]), "+f"((d)[1]), "+f"((d)[2]), "+f"((d)[3]) \
        : "r"((a)[0]), "r"((a)[1]), "r"((a)[2]), "r"((a)[3]), \
          "r"((b)[0]), "r"((b)[1]))

__device__ __forceinline__ uint32_t sw128(uint32_t off) {
    return off ^ ((off >> 3) & 0x70);
}

// ===========================================================================
// Scratch globals (no cudaMalloc allowed)
// ===========================================================================
__device__ __nv_bfloat16 g_hiA[(size_t)E_EDGES * 256];
__device__ __nv_bfloat16 g_loA[(size_t)E_EDGES * 256];
__device__ __nv_bfloat16 g_hiB[(size_t)E_EDGES * 256];
__device__ __nv_bfloat16 g_loB[(size_t)E_EDGES * 256];
__device__ float g_q  [(size_t)E_EDGES * 32];
__device__ float g_xnk[(size_t)E_EDGES * 96];

__device__ float g_W2q [256 * 32];   // W2 @ Wqk  (fp32, [k][n])
__device__ float g_Wcat[256 * 96];   // [W2 | W2@Wk] (fp32, [k][n])
// Transposed + split weights, [n][k] layout (K contiguous)
__device__ __nv_bfloat16 g_W0t_hi[256 * 256], g_W0t_lo[256 * 256];
__device__ __nv_bfloat16 g_W1t_hi[256 * 256], g_W1t_lo[256 * 256];
__device__ __nv_bfloat16 g_W2qt_hi[32 * 256], g_W2qt_lo[32 * 256];
__device__ __nv_bfloat16 g_Wct_hi[96 * 256],  g_Wct_lo[96 * 256];

__device__ __forceinline__ void split2(float v, __nv_bfloat16& h, __nv_bfloat16& l) {
    h = __float2bfloat16_rn(v);
    l = __float2bfloat16_rn(v - __bfloat162float(h));
}

// ===========================================================================
// prep1: fold head projections: g_W2q = W2@Wqk, g_Wcat = [W2 | W2@Wk]
// ===========================================================================
__global__ void prep_fold(const float* __restrict__ W2,
                          const float* __restrict__ Wqk,
                          const float* __restrict__ Wk) {
    __shared__ float sQ[64 * 32];
    __shared__ float sK[64 * 32];
    int tid = threadIdx.x;
    for (int i = tid; i < 64 * 32; i += 256) { sQ[i] = Wqk[i]; sK[i] = Wk[i]; }
    __syncthreads();
    int r = tid;
    float w2r[64];
#pragma unroll
    for (int j = 0; j < 64; ++j) w2r[j] = W2[r * 64 + j];
#pragma unroll 4
    for (int c = 0; c < 32; ++c) {
        float aq = 0.f, ak = 0.f;
#pragma unroll
        for (int j = 0; j < 64; ++j) {
            aq = fmaf(w2r[j], sQ[j * 32 + c], aq);
            ak = fmaf(w2r[j], sK[j * 32 + c], ak);
        }
        g_W2q[r * 32 + c]       = aq;
        g_Wcat[r * 96 + 64 + c] = ak;
    }
#pragma unroll
    for (int j = 0; j < 64; ++j) g_Wcat[r * 96 + j] = w2r[j];
}

// ===========================================================================
// prep2: transpose to [n][k] and split all GEMM weights to bf16 hi/lo
// ===========================================================================
__global__ void prep_transpose_split(const float* __restrict__ W0,
                                     const float* __restrict__ W1) {
    int t = blockIdx.x * 256 + threadIdx.x;
    int o = t >> 8, i = t & 255;
    __nv_bfloat16 h, l;
    split2(W0[i * 256 + o], h, l);  g_W0t_hi[t] = h;  g_W0t_lo[t] = l;
    split2(W1[i * 256 + o], h, l);  g_W1t_hi[t] = h;  g_W1t_lo[t] = l;
    if (o < 32) { split2(g_W2q[i * 32 + o], h, l);  g_W2qt_hi[t] = h; g_W2qt_lo[t] = l; }
    if (o < 96) { split2(g_Wcat[i * 96 + o], h, l); g_Wct_hi[t] = h;  g_Wct_lo[t] = l; }
}

// ===========================================================================
// convert fp32 activations -> bf16 hi/lo (one float4 per thread)
// ===========================================================================
__global__ void convert_split(const float* __restrict__ X,
                              __nv_bfloat16* __restrict__ hi,
                              __nv_bfloat16* __restrict__ lo) {
    size_t i = (size_t)blockIdx.x * blockDim.x + threadIdx.x;
    float4 v = ((const float4*)X)[i];
    float f[4] = {v.x, v.y, v.z, v.w};
    uint32_t hw[2], lw[2];
#pragma unroll
    for (int j = 0; j < 2; ++j) {
        __nv_bfloat16 h0, l0, h1, l1;
        split2(f[2 * j], h0, l0);
        split2(f[2 * j + 1], h1, l1);
        hw[j] = (uint32_t)__bfloat16_as_ushort(h0) | ((uint32_t)__bfloat16_as_ushort(h1) << 16);
        lw[j] = (uint32_t)__bfloat16_as_ushort(l0) | ((uint32_t)__bfloat16_as_ushort(l1) << 16);
    }
    ((uint2*)hi)[i] = make_uint2(hw[0], hw[1]);
    ((uint2*)lo)[i] = make_uint2(lw[0], lw[1]);
}

// ===========================================================================
// HMMA GEMM: C[M, N_TOT] = op( A[M,256] @ Bt[N_TOT,256]^T ), bf16x3 scheme:
//   C = Ah*Bh + Al*Bh + Ah*Bl
// Fused-chunk mainloop: 4 K-chunks of 64; per chunk load ALL four splits
// (Ah,Al,Bh,Bl) into one stage and run all 3 products -> 4 iterations,
// 192 MMAs/warp between barriers (vs 64 in the 12-pass version), A loaded once.
// BM=128, BN per template, 256 threads = 8 warps laid out 4(M) x 2(N).
// SPLIT_RELU: relu + re-split hi/lo bf16 (width 256). Else fp32 store (W_OUT).
// ===========================================================================
template <int BN, int W_OUT, bool SPLIT_RELU>
__global__ void __launch_bounds__(256)
hmma_gemm(const __nv_bfloat16* __restrict__ Ah, const __nv_bfloat16* __restrict__ Al,
          const __nv_bfloat16* __restrict__ Bh, const __nv_bfloat16* __restrict__ Bl,
          void* __restrict__ outHi, __nv_bfloat16* __restrict__ outLo) {
    constexpr int NB    = BN / 16;           // mma n-tiles per warp (warp covers BN/2 cols)
    constexpr int A_CH  = 128 * 128;         // bytes per A split per chunk (128 rows x 128B)
    constexpr int B_CH  = BN * 128;          // bytes per B split per chunk
    constexpr int STAGE = 2 * A_CH + 2 * B_CH;

    extern __shared__ char smem[];
    const uint32_t s0 = smem_u32(smem);

    const int tid  = threadIdx.x;
    const int lane = tid & 31;
    const int wid  = tid >> 5;
    const int m0w  = (wid & 3) * 32;
    const int n0w  = (wid >> 2) * (BN / 2);
    const int row0 = blockIdx.x * 128;
    const int col0 = blockIdx.y * BN;

    float acc[2][NB][4];
#pragma unroll
    for (int mi = 0; mi < 2; ++mi)
#pragma unroll
        for (int ni = 0; ni < NB; ++ni)
#pragma unroll
            for (int v = 0; v < 4; ++v) acc[mi][ni][v] = 0.f;

    auto loadChunk = [&](int c, int buf) {
        const int kk = c << 6;
        const uint32_t st = s0 + buf * STAGE;
        // A: both splits, 128 rows x 128B each
#pragma unroll
        for (int i = tid; i < 2048; i += 256) {
            int sp = i >> 10, idx = i & 1023, r = idx >> 3, c8 = idx & 7;
            const __nv_bfloat16* src =
                (sp ? Al : Ah) + (size_t)(row0 + r) * 256 + kk + c8 * 8;
            CP_ASYNC16(st + sp * A_CH + sw128(r * 128 + c8 * 16), src);
        }
        // B: both splits, BN rows x 128B each
#pragma unroll
        for (int i = tid; i < 2 * BN * 8; i += 256) {
            int sp = i / (BN * 8), idx = i % (BN * 8), n = idx >> 3, c8 = idx & 7;
            const __nv_bfloat16* src =
                (sp ? Bl : Bh) + (size_t)(col0 + n) * 256 + kk + c8 * 8;
            CP_ASYNC16(st + 2 * A_CH + sp * B_CH + sw128(n * 128 + c8 * 16), src);
        }
    };

    loadChunk(0, 0);
    CP_COMMIT();

#pragma unroll 1
    for (int c = 0; c < 4; ++c) {
        if (c < 3) {
            loadChunk(c + 1, (c + 1) & 1);
            CP_COMMIT();
            CP_WAIT(1);
        } else {
            CP_WAIT(0);
        }
        __syncthreads();

        const uint32_t st = s0 + (c & 1) * STAGE;
        const uint32_t da = st;
        const uint32_t db = st + 2 * A_CH;
#pragma unroll
        for (int ks = 0; ks < 4; ++ks) {
            uint32_t ah[2][4], al[2][4];
#pragma unroll
            for (int mi = 0; mi < 2; ++mi) {
                uint32_t aoff = sw128((m0w + mi * 16 + (lane & 15)) * 128 +
                                      ks * 32 + (lane >> 4) * 16);
                ldsm_x4(ah[mi], da + aoff);
                ldsm_x4(al[mi], da + A_CH + aoff);
            }
            uint32_t bh[NB][2], bl[NB][2];
#pragma unroll
            for (int np = 0; np < NB / 2; ++np) {
                uint32_t boff = sw128((n0w + np * 16 + (lane >> 4) * 8 + (lane & 7)) * 128 +
                                      ks * 32 + ((lane >> 3) & 1) * 16);
                ldsm_x4(&bh[2 * np][0], db + boff);
                ldsm_x4(&bl[2 * np][0], db + B_CH + boff);
            }
            // product-major order: accumulations into the same acc[mi][ni]
            // are separated by 2*NB independent MMAs (breaks RAW chains)
#pragma unroll
            for (int mi = 0; mi < 2; ++mi)
#pragma unroll
                for (int ni = 0; ni < NB; ++ni)
                    MMA16816(acc[mi][ni], ah[mi], bh[ni]);
#pragma unroll
            for (int mi = 0; mi < 2; ++mi)
#pragma unroll
                for (int ni = 0; ni < NB; ++ni)
                    MMA16816(acc[mi][ni], al[mi], bh[ni]);
#pragma unroll
            for (int mi = 0; mi < 2; ++mi)
#pragma unroll
                for (int ni = 0; ni < NB; ++ni)
                    MMA16816(acc[mi][ni], ah[mi], bl[ni]);
        }
        __syncthreads();
    }

    // ---- epilogue ----
    const int rbase = row0 + m0w + (lane >> 2);
#pragma unroll
    for (int mi = 0; mi < 2; ++mi) {
        const int r0 = rbase + mi * 16;
#pragma unroll
        for (int ni = 0; ni < NB; ++ni) {
            const int c = col0 + n0w + ni * 8 + (lane & 3) * 2;
            if (SPLIT_RELU) {
                __nv_bfloat16* hi = (__nv_bfloat16*)outHi;
#pragma unroll
                for (int h = 0; h < 2; ++h) {
                    float v0 = fmaxf(acc[mi][ni][2 * h],     0.f);
                    float v1 = fmaxf(acc[mi][ni][2 * h + 1], 0.f);
                    __nv_bfloat16 h0, l0, h1, l1;
                    split2(v0, h0, l0);
                    split2(v1, h1, l1);
                    size_t off = (size_t)(r0 + h * 8) * 256 + c;
                    *(uint32_t*)(hi + off)    = (uint32_t)__bfloat16_as_ushort(h0) |
                                                ((uint32_t)__bfloat16_as_ushort(h1) << 16);
                    *(uint32_t*)(outLo + off) = (uint32_t)__bfloat16_as_ushort(l0) |
                                                ((uint32_t)__bfloat16_as_ushort(l1) << 16);
                }
            } else {
                float* of = (float*)outHi;
                *(float2*)(of + (size_t)r0 * W_OUT + c) =
                    make_float2(acc[mi][ni][0], acc[mi][ni][1]);
                *(float2*)(of + (size_t)(r0 + 8) * W_OUT + c) =
                    make_float2(acc[mi][ni][2], acc[mi][ni][3]);
            }
        }
    }
}

// ===========================================================================
// Edge finalize: one warp per edge.
//   s = sigmoid(dot(q,k)) * ppr;  atomicAdd(out[ppr_idx][:], xn[:] * s)
// g_xnk per edge: [0:64) x_neighbor, [64:96) k
// ===========================================================================
__global__ void edge_finalize(const float* __restrict__ ppr_scores,
                              const int* __restrict__ ppr_idx,
                              float* __restrict__ out) {
    int gtid = blockIdx.x * blockDim.x + threadIdx.x;
    int edge = gtid >> 5;
    int lane = gtid & 31;
    if (edge >= E_EDGES) return;

    const float* xnk = g_xnk + (size_t)edge * 96;
    float p = g_q[(size_t)edge * 32 + lane] * xnk[64 + lane];
#pragma unroll
    for (int off = 16; off > 0; off >>= 1)
        p += __shfl_xor_sync(0xffffffffu, p, off);

    float s = ppr_scores[edge] / (1.f + expf(-p));
    int g = ppr_idx[edge];
    atomicAdd(&out[(size_t)g * 64 + lane],      xnk[lane]      * s);
    atomicAdd(&out[(size_t)g * 64 + 32 + lane], xnk[32 + lane] * s);
}

// ===========================================================================
// Launch sequence (graph-capturable)
// ===========================================================================
extern "C" void kernel_launch(void* const* d_in, const int* in_sizes, int n_in,
                              void* d_out, int out_size) {
    const float* source_attr   = (const float*)d_in[0];
    const float* neighbor_attr = (const float*)d_in[1];
    const float* ppr_scores    = (const float*)d_in[2];
    const int*   ppr_idx       = (const int*)  d_in[3];
    const float* W0  = (const float*)d_in[5];
    const float* W1  = (const float*)d_in[6];
    const float* W2  = (const float*)d_in[7];
    const float* Wqk = (const float*)d_in[8];
    const float* Wk  = (const float*)d_in[9];
    float* out = (float*)d_out;

    __nv_bfloat16 *hiA, *loA, *hiB, *loB;
    __nv_bfloat16 *w0h, *w0l, *w1h, *w1l, *w2qh, *w2ql, *wch, *wcl;
    float *qbuf, *xnk;
    cudaGetSymbolAddress((void**)&hiA, g_hiA);
    cudaGetSymbolAddress((void**)&loA, g_loA);
    cudaGetSymbolAddress((void**)&hiB, g_hiB);
    cudaGetSymbolAddress((void**)&loB, g_loB);
    cudaGetSymbolAddress((void**)&qbuf, g_q);
    cudaGetSymbolAddress((void**)&xnk,  g_xnk);
    cudaGetSymbolAddress((void**)&w0h, g_W0t_hi);
    cudaGetSymbolAddress((void**)&w0l, g_W0t_lo);
    cudaGetSymbolAddress((void**)&w1h, g_W1t_hi);
    cudaGetSymbolAddress((void**)&w1l, g_W1t_lo);
    cudaGetSymbolAddress((void**)&w2qh, g_W2qt_hi);
    cudaGetSymbolAddress((void**)&w2ql, g_W2qt_lo);
    cudaGetSymbolAddress((void**)&wch, g_Wct_hi);
    cudaGetSymbolAddress((void**)&wcl, g_Wct_lo);

    // dynamic smem: 2 stages x (Ah+Al+Bh+Bl chunks)
    constexpr int SM128 = 2 * (2 * 128 * 128 + 2 * 128 * 128);  // 131072
    constexpr int SM96  = 2 * (2 * 128 * 128 + 2 * 96 * 128);   // 114688
    constexpr int SM32  = 2 * (2 * 128 * 128 + 2 * 32 * 128);   //  81920
    cudaFuncSetAttribute(hmma_gemm<128, 256, true>,
                         cudaFuncAttributeMaxDynamicSharedMemorySize, SM128);
    cudaFuncSetAttribute(hmma_gemm<96, 96, false>,
                         cudaFuncAttributeMaxDynamicSharedMemorySize, SM96);
    cudaFuncSetAttribute(hmma_gemm<32, 32, false>,
                         cudaFuncAttributeMaxDynamicSharedMemorySize, SM32);

    const int MB = E_EDGES / 128;  // 3125 row tiles

    prep_fold<<<1, 256>>>(W2, Wqk, Wk);
    prep_transpose_split<<<256, 256>>>(W0, W1);
    cudaMemsetAsync(d_out, 0, (size_t)out_size * sizeof(float));

    // ---- source branch: only q survives ----
    convert_split<<<100000, 256>>>(source_attr, hiA, loA);
    hmma_gemm<128, 256, true ><<<dim3(MB, 2), 256, SM128>>>(hiA, loA, w0h, w0l, hiB, loB);
    hmma_gemm<128, 256, true ><<<dim3(MB, 2), 256, SM128>>>(hiB, loB, w1h, w1l, hiA, loA);
    hmma_gemm< 32,  32, false><<<dim3(MB, 1), 256, SM32 >>>(hiA, loA, w2qh, w2ql, qbuf, nullptr);

    // ---- neighbor branch: [x_neighbor(64) | k(32)] fused as N=96 ----
    convert_split<<<100000, 256>>>(neighbor_attr, hiA, loA);
    hmma_gemm<128, 256, true ><<<dim3(MB, 2), 256, SM128>>>(hiA, loA, w0h, w0l, hiB, loB);
    hmma_gemm<128, 256, true ><<<dim3(MB, 2), 256, SM128>>>(hiB, loB, w1h, w1l, hiA, loA);
    hmma_gemm< 96,  96, false><<<dim3(MB, 1), 256, SM96 >>>(hiA, loA, wch, wcl, xnk, nullptr);

    // ---- attention + segment scatter ----
    edge_finalize<<<(E_EDGES * 32 + 255) / 256, 256>>>(ppr_scores, ppr_idx, out);
}

// round 8
// speedup vs baseline: 1.3541x; 1.2007x over previous
#include <cuda_runtime.h>
#include <cuda_bf16.h>
#include <math.h>
#include <stdint.h>

#define E_EDGES 400000
#define NGROUPS 25000

// ===========================================================================
// PTX helpers (sm_80-class only — toolchain targets plain sm_103, no tcgen05)
// ===========================================================================
__device__ __forceinline__ uint32_t smem_u32(const void* p) {
    uint32_t a;
    asm("{ .reg .u64 t; cvta.to.shared.u64 t, %1; cvt.u32.u64 %0, t; }"
        : "=r"(a) : "l"(p));
    return a;
}

#define CP_ASYNC16(sm, gm) \
    asm volatile("cp.async.cg.shared.global [%0], [%1], 16;" \
        :: "r"(sm), "l"(gm) : "memory")
#define CP_COMMIT() asm volatile("cp.async.commit_group;" ::: "memory")
#define CP_WAIT(n)  asm volatile("cp.async.wait_group %0;" :: "n"(n) : "memory")

__device__ __forceinline__ void ldsm_x4(uint32_t* d, uint32_t addr) {
    asm volatile("ldmatrix.sync.aligned.m8n8.x4.shared.b16 {%0,%1,%2,%3}, [%4];"
        : "=r"(d[0]), "=r"(d[1]), "=r"(d[2]), "=r"(d[3]) : "r"(addr));
}

#define MMA16816(d, a, b) \
    asm volatile("mma.sync.aligned.m16n8k16.row.col.f32.bf16.bf16.f32 " \
        "{%0,%1,%2,%3}, {%4,%5,%6,%7}, {%8,%9}, {%0,%1,%2,%3};" \
        : "+f"((d)[0]), "+f"((d)[1]), "+f"((d)[2]), "+f"((d)[3]) \
        : "r"((a)[0]), "r"((a)[1]), "r"((a)[2]), "r"((a)[3]), \
          "r"((b)[0]), "r"((b)[1]))

// SW64 swizzle for 64-byte rows (BK=32 bf16): XOR addr bits [5:4] with [8:7].
// Verified conflict-free for ldmatrix 8-row phases at 64B row stride.
__device__ __forceinline__ uint32_t sw(uint32_t off) {
    return off ^ ((off >> 3) & 0x30);
}

// ===========================================================================
// Scratch globals (no cudaMalloc allowed)
// ===========================================================================
__device__ __nv_bfloat16 g_hiA[(size_t)E_EDGES * 256];
__device__ __nv_bfloat16 g_loA[(size_t)E_EDGES * 256];
__device__ __nv_bfloat16 g_hiB[(size_t)E_EDGES * 256];
__device__ __nv_bfloat16 g_loB[(size_t)E_EDGES * 256];
__device__ float g_q  [(size_t)E_EDGES * 32];
__device__ float g_xnk[(size_t)E_EDGES * 96];

__device__ float g_W2q [256 * 32];   // W2 @ Wqk  (fp32, [k][n])
__device__ float g_Wcat[256 * 96];   // [W2 | W2@Wk] (fp32, [k][n])
// Transposed + split weights, [n][k] layout (K contiguous)
__device__ __nv_bfloat16 g_W0t_hi[256 * 256], g_W0t_lo[256 * 256];
__device__ __nv_bfloat16 g_W1t_hi[256 * 256], g_W1t_lo[256 * 256];
__device__ __nv_bfloat16 g_W2qt_hi[32 * 256], g_W2qt_lo[32 * 256];
__device__ __nv_bfloat16 g_Wct_hi[96 * 256],  g_Wct_lo[96 * 256];

__device__ __forceinline__ void split2(float v, __nv_bfloat16& h, __nv_bfloat16& l) {
    h = __float2bfloat16_rn(v);
    l = __float2bfloat16_rn(v - __bfloat162float(h));
}

// ===========================================================================
// prep1: fold head projections: g_W2q = W2@Wqk, g_Wcat = [W2 | W2@Wk]
// ===========================================================================
__global__ void prep_fold(const float* __restrict__ W2,
                          const float* __restrict__ Wqk,
                          const float* __restrict__ Wk) {
    __shared__ float sQ[64 * 32];
    __shared__ float sK[64 * 32];
    int tid = threadIdx.x;
    for (int i = tid; i < 64 * 32; i += 256) { sQ[i] = Wqk[i]; sK[i] = Wk[i]; }
    __syncthreads();
    int r = tid;
    float w2r[64];
#pragma unroll
    for (int j = 0; j < 64; ++j) w2r[j] = W2[r * 64 + j];
#pragma unroll 4
    for (int c = 0; c < 32; ++c) {
        float aq = 0.f, ak = 0.f;
#pragma unroll
        for (int j = 0; j < 64; ++j) {
            aq = fmaf(w2r[j], sQ[j * 32 + c], aq);
            ak = fmaf(w2r[j], sK[j * 32 + c], ak);
        }
        g_W2q[r * 32 + c]       = aq;
        g_Wcat[r * 96 + 64 + c] = ak;
    }
#pragma unroll
    for (int j = 0; j < 64; ++j) g_Wcat[r * 96 + j] = w2r[j];
}

// ===========================================================================
// prep2: transpose to [n][k] and split all GEMM weights to bf16 hi/lo
// ===========================================================================
__global__ void prep_transpose_split(const float* __restrict__ W0,
                                     const float* __restrict__ W1) {
    int t = blockIdx.x * 256 + threadIdx.x;
    int o = t >> 8, i = t & 255;
    __nv_bfloat16 h, l;
    split2(W0[i * 256 + o], h, l);  g_W0t_hi[t] = h;  g_W0t_lo[t] = l;
    split2(W1[i * 256 + o], h, l);  g_W1t_hi[t] = h;  g_W1t_lo[t] = l;
    if (o < 32) { split2(g_W2q[i * 32 + o], h, l);  g_W2qt_hi[t] = h; g_W2qt_lo[t] = l; }
    if (o < 96) { split2(g_Wcat[i * 96 + o], h, l); g_Wct_hi[t] = h;  g_Wct_lo[t] = l; }
}

// ===========================================================================
// HMMA GEMM, bf16x3: C = Ah*Bh + Al*Bh + Ah*Bl.
// BM=128, BK=32, 8 K-chunks, double-buffered, SW64-swizzled 64B smem rows.
// 256 threads = 8 warps (4M x 2N), 2 CTAs/SM (launch_bounds(256,2), 64KB smem).
// FP32A: A is fp32 in gmem; loaded via LDG float4 (hidden under MMA section),
//        converted to hi/lo bf16 in-register, STS'd to the next stage.
// SPLIT_RELU: relu + re-split hi/lo bf16 (width 256). Else fp32 store (W_OUT).
// ===========================================================================
template <int BN, int W_OUT, bool SPLIT_RELU, bool FP32A>
__global__ void __launch_bounds__(256, 2)
hmma_gemm(const void* __restrict__ Ah_, const __nv_bfloat16* __restrict__ Al,
          const __nv_bfloat16* __restrict__ Bh, const __nv_bfloat16* __restrict__ Bl,
          void* __restrict__ outHi, __nv_bfloat16* __restrict__ outLo) {
    constexpr int NB    = BN / 16;           // n8-tile pairs per warp... (warp covers BN/2)
    constexpr int A_CH  = 128 * 64;          // bytes per A split per chunk (128 rows x 64B)
    constexpr int B_CH  = BN * 64;
    constexpr int STAGE = 2 * A_CH + 2 * B_CH;

    extern __shared__ char smem[];
    const uint32_t s0 = smem_u32(smem);

    const int tid  = threadIdx.x;
    const int lane = tid & 31;
    const int wid  = tid >> 5;
    const int m0w  = (wid & 3) * 32;
    const int n0w  = (wid >> 2) * (BN / 2);
    const int row0 = blockIdx.x * 128;
    const int col0 = blockIdx.y * BN;

    const float* Afp = (const float*)Ah_;
    const __nv_bfloat16* Ah = (const __nv_bfloat16*)Ah_;

    float acc[2][NB][4];
#pragma unroll
    for (int mi = 0; mi < 2; ++mi)
#pragma unroll
        for (int ni = 0; ni < NB; ++ni)
#pragma unroll
            for (int v = 0; v < 4; ++v) acc[mi][ni][v] = 0.f;

    float4 pf[4];  // FP32A prefetch: 128x32 fp32 chunk = 4 float4/thread

    auto loadB = [&](int c, int buf) {
        const int kk = c << 5;
#pragma unroll
        for (int i = tid; i < 2 * BN * 4; i += 256) {
            int sp = i / (BN * 4), idx = i % (BN * 4), n = idx >> 2, g = idx & 3;
            const __nv_bfloat16* src =
                (sp ? Bl : Bh) + (size_t)(col0 + n) * 256 + kk + g * 8;
            CP_ASYNC16(s0 + buf * STAGE + 2 * A_CH + sp * B_CH + sw(n * 64 + g * 16), src);
        }
    };
    auto loadA_cp = [&](int c, int buf) {
        const int kk = c << 5;
#pragma unroll
        for (int i = tid; i < 1024; i += 256) {
            int sp = i >> 9, idx = i & 511, r = idx >> 2, g = idx & 3;
            const __nv_bfloat16* src =
                (sp ? Al : Ah) + (size_t)(row0 + r) * 256 + kk + g * 8;
            CP_ASYNC16(s0 + buf * STAGE + sp * A_CH + sw(r * 64 + g * 16), src);
        }
    };
    auto ldA_f32 = [&](int c) {
        const int kk = c << 5;
#pragma unroll
        for (int j = 0; j < 4; ++j) {
            int f4 = tid + 256 * j;
            int r = f4 >> 3, c4 = f4 & 7;
            pf[j] = *(const float4*)(Afp + (size_t)(row0 + r) * 256 + kk + c4 * 4);
        }
    };
    auto stA_f32 = [&](int buf) {
#pragma unroll
        for (int j = 0; j < 4; ++j) {
            int f4 = tid + 256 * j;
            int r = f4 >> 3, c4 = f4 & 7;
            __nv_bfloat16 h0, l0, h1, l1, h2, l2, h3, l3;
            split2(pf[j].x, h0, l0); split2(pf[j].y, h1, l1);
            split2(pf[j].z, h2, l2); split2(pf[j].w, h3, l3);
            uint2 hw = make_uint2(
                (uint32_t)__bfloat16_as_ushort(h0) | ((uint32_t)__bfloat16_as_ushort(h1) << 16),
                (uint32_t)__bfloat16_as_ushort(h2) | ((uint32_t)__bfloat16_as_ushort(h3) << 16));
            uint2 lw = make_uint2(
                (uint32_t)__bfloat16_as_ushort(l0) | ((uint32_t)__bfloat16_as_ushort(l1) << 16),
                (uint32_t)__bfloat16_as_ushort(l2) | ((uint32_t)__bfloat16_as_ushort(l3) << 16));
            uint32_t off = buf * STAGE + sw(r * 64 + c4 * 8);
            *(uint2*)(smem + off)        = hw;
            *(uint2*)(smem + off + A_CH) = lw;
        }
    };

    // ---- prologue ----
    if (FP32A) {
        ldA_f32(0);
        loadB(0, 0);
        CP_COMMIT();
        stA_f32(0);
    } else {
        loadA_cp(0, 0);
        loadB(0, 0);
        CP_COMMIT();
    }

#pragma unroll 1
    for (int c = 0; c < 8; ++c) {
        if (c < 7) {
            if (FP32A) {
                ldA_f32(c + 1);
                loadB(c + 1, (c + 1) & 1);
            } else {
                loadA_cp(c + 1, (c + 1) & 1);
                loadB(c + 1, (c + 1) & 1);
            }
            CP_COMMIT();
            CP_WAIT(1);
        } else {
            CP_WAIT(0);
        }
        __syncthreads();

        const uint32_t st = s0 + (c & 1) * STAGE;
        const uint32_t da = st;
        const uint32_t db = st + 2 * A_CH;
#pragma unroll
        for (int ks = 0; ks < 2; ++ks) {
            uint32_t ah[2][4], al[2][4];
#pragma unroll
            for (int mi = 0; mi < 2; ++mi) {
                uint32_t aoff = sw((m0w + mi * 16 + (lane & 15)) * 64 +
                                   ks * 32 + (lane >> 4) * 16);
                ldsm_x4(ah[mi], da + aoff);
                ldsm_x4(al[mi], da + A_CH + aoff);
            }
#pragma unroll
            for (int np = 0; np < NB / 2; ++np) {
                uint32_t boff = sw((n0w + np * 16 + (lane >> 4) * 8 + (lane & 7)) * 64 +
                                   ks * 32 + ((lane >> 3) & 1) * 16);
                uint32_t bh4[4], bl4[4];
                ldsm_x4(bh4, db + boff);
                ldsm_x4(bl4, db + B_CH + boff);
                // 12 MMAs; dependent accs separated by >=3 independent MMAs
#pragma unroll
                for (int mi = 0; mi < 2; ++mi) MMA16816(acc[mi][2 * np],     ah[mi], bh4);
#pragma unroll
                for (int mi = 0; mi < 2; ++mi) MMA16816(acc[mi][2 * np + 1], ah[mi], bh4 + 2);
#pragma unroll
                for (int mi = 0; mi < 2; ++mi) MMA16816(acc[mi][2 * np],     al[mi], bh4);
#pragma unroll
                for (int mi = 0; mi < 2; ++mi) MMA16816(acc[mi][2 * np + 1], al[mi], bh4 + 2);
#pragma unroll
                for (int mi = 0; mi < 2; ++mi) MMA16816(acc[mi][2 * np],     ah[mi], bl4);
#pragma unroll
                for (int mi = 0; mi < 2; ++mi) MMA16816(acc[mi][2 * np + 1], ah[mi], bl4 + 2);
            }
        }
        if (FP32A && c < 7) stA_f32((c + 1) & 1);
        __syncthreads();
    }

    // ---- epilogue ----
    const int rbase = row0 + m0w + (lane >> 2);
#pragma unroll
    for (int mi = 0; mi < 2; ++mi) {
        const int r0 = rbase + mi * 16;
#pragma unroll
        for (int ni = 0; ni < NB; ++ni) {
            const int c = col0 + n0w + ni * 8 + (lane & 3) * 2;
            if (SPLIT_RELU) {
                __nv_bfloat16* hi = (__nv_bfloat16*)outHi;
#pragma unroll
                for (int h = 0; h < 2; ++h) {
                    float v0 = fmaxf(acc[mi][ni][2 * h],     0.f);
                    float v1 = fmaxf(acc[mi][ni][2 * h + 1], 0.f);
                    __nv_bfloat16 h0, l0, h1, l1;
                    split2(v0, h0, l0);
                    split2(v1, h1, l1);
                    size_t off = (size_t)(r0 + h * 8) * 256 + c;
                    *(uint32_t*)(hi + off)    = (uint32_t)__bfloat16_as_ushort(h0) |
                                                ((uint32_t)__bfloat16_as_ushort(h1) << 16);
                    *(uint32_t*)(outLo + off) = (uint32_t)__bfloat16_as_ushort(l0) |
                                                ((uint32_t)__bfloat16_as_ushort(l1) << 16);
                }
            } else {
                float* of = (float*)outHi;
                *(float2*)(of + (size_t)r0 * W_OUT + c) =
                    make_float2(acc[mi][ni][0], acc[mi][ni][1]);
                *(float2*)(of + (size_t)(r0 + 8) * W_OUT + c) =
                    make_float2(acc[mi][ni][2], acc[mi][ni][3]);
            }
        }
    }
}

// ===========================================================================
// Edge finalize: one warp per edge.
// ===========================================================================
__global__ void edge_finalize(const float* __restrict__ ppr_scores,
                              const int* __restrict__ ppr_idx,
                              float* __restrict__ out) {
    int gtid = blockIdx.x * blockDim.x + threadIdx.x;
    int edge = gtid >> 5;
    int lane = gtid & 31;
    if (edge >= E_EDGES) return;

    const float* xnk = g_xnk + (size_t)edge * 96;
    float p = g_q[(size_t)edge * 32 + lane] * xnk[64 + lane];
#pragma unroll
    for (int off = 16; off > 0; off >>= 1)
        p += __shfl_xor_sync(0xffffffffu, p, off);

    float s = ppr_scores[edge] / (1.f + expf(-p));
    int g = ppr_idx[edge];
    atomicAdd(&out[(size_t)g * 64 + lane],      xnk[lane]      * s);
    atomicAdd(&out[(size_t)g * 64 + 32 + lane], xnk[32 + lane] * s);
}

// ===========================================================================
// Launch sequence (graph-capturable)
// ===========================================================================
extern "C" void kernel_launch(void* const* d_in, const int* in_sizes, int n_in,
                              void* d_out, int out_size) {
    const float* source_attr   = (const float*)d_in[0];
    const float* neighbor_attr = (const float*)d_in[1];
    const float* ppr_scores    = (const float*)d_in[2];
    const int*   ppr_idx       = (const int*)  d_in[3];
    const float* W0  = (const float*)d_in[5];
    const float* W1  = (const float*)d_in[6];
    const float* W2  = (const float*)d_in[7];
    const float* Wqk = (const float*)d_in[8];
    const float* Wk  = (const float*)d_in[9];
    float* out = (float*)d_out;

    __nv_bfloat16 *hiA, *loA, *hiB, *loB;
    __nv_bfloat16 *w0h, *w0l, *w1h, *w1l, *w2qh, *w2ql, *wch, *wcl;
    float *qbuf, *xnk;
    cudaGetSymbolAddress((void**)&hiA, g_hiA);
    cudaGetSymbolAddress((void**)&loA, g_loA);
    cudaGetSymbolAddress((void**)&hiB, g_hiB);
    cudaGetSymbolAddress((void**)&loB, g_loB);
    cudaGetSymbolAddress((void**)&qbuf, g_q);
    cudaGetSymbolAddress((void**)&xnk,  g_xnk);
    cudaGetSymbolAddress((void**)&w0h, g_W0t_hi);
    cudaGetSymbolAddress((void**)&w0l, g_W0t_lo);
    cudaGetSymbolAddress((void**)&w1h, g_W1t_hi);
    cudaGetSymbolAddress((void**)&w1l, g_W1t_lo);
    cudaGetSymbolAddress((void**)&w2qh, g_W2qt_hi);
    cudaGetSymbolAddress((void**)&w2ql, g_W2qt_lo);
    cudaGetSymbolAddress((void**)&wch, g_Wct_hi);
    cudaGetSymbolAddress((void**)&wcl, g_Wct_lo);

    // dynamic smem: 2 stages x (2*A_CH + 2*B_CH), BK=32
    constexpr int SM128 = 2 * (2 * 128 * 64 + 2 * 128 * 64);  // 65536
    constexpr int SM96  = 2 * (2 * 128 * 64 + 2 * 96 * 64);   // 57344
    constexpr int SM32  = 2 * (2 * 128 * 64 + 2 * 32 * 64);   // 40960
    cudaFuncSetAttribute(hmma_gemm<128, 256, true, true>,
                         cudaFuncAttributeMaxDynamicSharedMemorySize, SM128);
    cudaFuncSetAttribute(hmma_gemm<128, 256, true, false>,
                         cudaFuncAttributeMaxDynamicSharedMemorySize, SM128);
    cudaFuncSetAttribute(hmma_gemm<96, 96, false, false>,
                         cudaFuncAttributeMaxDynamicSharedMemorySize, SM96);
    cudaFuncSetAttribute(hmma_gemm<32, 32, false, false>,
                         cudaFuncAttributeMaxDynamicSharedMemorySize, SM32);

    const int MB = E_EDGES / 128;  // 3125 row tiles

    prep_fold<<<1, 256>>>(W2, Wqk, Wk);
    prep_transpose_split<<<256, 256>>>(W0, W1);
    cudaMemsetAsync(d_out, 0, (size_t)out_size * sizeof(float));

    // ---- source branch: only q survives ----
    hmma_gemm<128, 256, true, true ><<<dim3(MB, 2), 256, SM128>>>(
        source_attr, nullptr, w0h, w0l, hiB, loB);
    hmma_gemm<128, 256, true, false><<<dim3(MB, 2), 256, SM128>>>(
        hiB, loB, w1h, w1l, hiA, loA);
    hmma_gemm< 32,  32, false, false><<<dim3(MB, 1), 256, SM32>>>(
        hiA, loA, w2qh, w2ql, qbuf, nullptr);

    // ---- neighbor branch: [x_neighbor(64) | k(32)] fused as N=96 ----
    hmma_gemm<128, 256, true, true ><<<dim3(MB, 2), 256, SM128>>>(
        neighbor_attr, nullptr, w0h, w0l, hiB, loB);
    hmma_gemm<128, 256, true, false><<<dim3(MB, 2), 256, SM128>>>(
        hiB, loB, w1h, w1l, hiA, loA);
    hmma_gemm< 96,  96, false, false><<<dim3(MB, 1), 256, SM96>>>(
        hiA, loA, wch, wcl, xnk, nullptr);

    // ---- attention + segment scatter ----
    edge_finalize<<<(E_EDGES * 32 + 255) / 256, 256>>>(ppr_scores, ppr_idx, out);
}